// round 15
// baseline (speedup 1.0000x reference)
#include <cuda_runtime.h>
#include <cuda_bf16.h>
#include <cstdint>

#define SEQ    8192
#define VOCAB  256
#define HID    2048
#define OUTN   256

#define NCTA     148
#define NTHREADS 256          // warps 0-6: 8 dot-rows each; warp 7: sync/gather
#define K_SM     1792         // k<1792 in SMEM (224 uint4/row); k in [1792,2048) via prefetched global tail
#define ROW_B    (K_SM * 2)   // 3584 bytes per SMEM weight row
#define MAX_ROWS 56
#define NGRP     74           // CTAs per counter group (A: 0-73, B: 74-147)
// weights 200704 + h 8192 + zbuf 256 = 209152 <= 232448 (+16B static)
#define SMEM_RECUR (MAX_ROWS * ROW_B + HID * 4 + 64 * 4)

// ---------------- device scratch (module-scope: no runtime allocs) ----------------
__device__ __nv_bfloat16 d_Uh[(size_t)4 * HID * HID]; // [(j*4+g)*HID + k] = bf16(U_g[k][j])
__device__ float  d_G[(size_t)4 * VOCAB * HID];       // [(v*HID + j)*4 + g] = emb[v]@W_g + b_g + c_g
__device__ float  d_hs[(size_t)SEQ * HID];            // h history for output GEMM
__device__ float  d_hbuf[2][HID];                     // double-buffered cross-CTA h
__device__ float  d_cfinal[HID];
__device__ unsigned d_barcnt;                         // startup barrier (legacy, replay-safe)
__device__ unsigned d_bargen;
__device__ unsigned long long d_cntA;                 // monotonic arrivals, CTAs 0-73
__device__ unsigned long long d_cntB;                 // monotonic arrivals, CTAs 74-147

struct GateArgs {
    const float* W[4];
    const float* b[4];
    const float* cb[4];
};
struct UArgs {
    const float* U[4];
};

// packed bf16x2 -> f32x2 expand + packed FMA: acc(f32x2) += h(f32x2) * expand(w)
__device__ __forceinline__ void fma2_bf(unsigned w, unsigned long long hp,
                                        unsigned long long& acc)
{
    asm("{\n\t"
        ".reg .b32 lo, hi;\n\t"
        ".reg .b64 wp;\n\t"
        "shl.b32 lo, %1, 16;\n\t"
        "and.b32 hi, %1, 0xffff0000;\n\t"
        "mov.b64 wp, {lo, hi};\n\t"
        "fma.rn.f32x2 %0, %2, wp, %0;\n\t"
        "}" : "+l"(acc) : "r"(w), "l"(hp));
}
__device__ __forceinline__ float acc2_sum(unsigned long long a)
{
    return __uint_as_float((unsigned)a) + __uint_as_float((unsigned)(a >> 32));
}

__device__ __forceinline__ void red_add_release(unsigned long long* p)
{
    asm volatile("red.release.gpu.global.add.u64 [%0], 1;" :: "l"(p) : "memory");
}
__device__ __forceinline__ unsigned long long ld_acq64(const unsigned long long* p)
{
    unsigned long long v;
    asm volatile("ld.acquire.gpu.global.u64 %0, [%1];" : "=l"(v) : "l"(p) : "memory");
    return v;
}
__device__ __forceinline__ void bar_sync(int id, int nthr)
{
    asm volatile("bar.sync %0, %1;" :: "r"(id), "r"(nthr) : "memory");
}

// ============================================================================
// Kernel 1: gate tables  G[v][j][g] = sum_k emb[v][k]*W_g[k][j] + b_g[j] + c_g[j]
// ============================================================================
__global__ void __launch_bounds__(256) prep_tables_kernel(const float* __restrict__ emb, GateArgs ga)
{
    const int g  = blockIdx.y;
    const float* __restrict__ W  = ga.W[g];
    const float* __restrict__ b  = ga.b[g];
    const float* __restrict__ cb = ga.cb[g];
    const int v0 = blockIdx.x * 8;
    const int tid = threadIdx.x;

    __shared__ float es[8 * 256];
    for (int i = tid; i < 8 * 256; i += 256)
        es[i] = emb[(size_t)(v0 + (i >> 8)) * VOCAB + (i & 255)];
    __syncthreads();

    for (int jj = 0; jj < 8; jj++) {
        const int j = tid + (jj << 8);
        float acc[8];
        #pragma unroll
        for (int v = 0; v < 8; v++) acc[v] = 0.f;
        #pragma unroll 4
        for (int k = 0; k < 256; k++) {
            const float wv = W[(size_t)k * HID + j];
            #pragma unroll
            for (int v = 0; v < 8; v++)
                acc[v] = fmaf(es[(v << 8) + k], wv, acc[v]);
        }
        const float bias = b[j] + cb[j];
        #pragma unroll
        for (int v = 0; v < 8; v++)
            d_G[(((size_t)(v0 + v) * HID) + j) * 4 + g] = acc[v] + bias;
    }
}

// ============================================================================
// Kernel 2: transpose + bf16-convert U:  d_Uh[(j*4+g)*HID + k] = bf16(U_g[k][j])
// ============================================================================
__global__ void __launch_bounds__(1024) prep_weights_kernel(UArgs ua)
{
    const int g = blockIdx.z;
    const float* __restrict__ U = ua.U[g];
    __shared__ float tile[32][33];
    const int j0 = blockIdx.x * 32;
    const int k0 = blockIdx.y * 32;
    const int tx = threadIdx.x, ty = threadIdx.y;

    tile[ty][tx] = U[(size_t)(k0 + ty) * HID + (j0 + tx)];
    __syncthreads();
    d_Uh[((size_t)(j0 + ty) * 4 + g) * HID + (k0 + tx)] = __float2bfloat16(tile[tx][ty]);
}

// no-op alignment kernel (keeps lstm_recur at ncu launch index 5)
__global__ void nop_kernel() {}

// ============================================================================
// Kernel 3: persistent recurrence. 148 CTAs (1/SM).
// Warps 0-6: dots (8 rows each). Warp 7: counter polling + h gathers.
// Split-h pipelining: lower-k dots overlap upper-half sync+gather.
// ============================================================================
__device__ __forceinline__ float sigmoid_f(float z)
{
    return 1.f / (1.f + __expf(-z));
}
__device__ __forceinline__ float tanh_f(float z)
{
    const float e = __expf(2.f * z);
    return 1.f - __fdividef(2.f, 1.f + e);
}

__global__ void __launch_bounds__(NTHREADS, 1) lstm_recur_kernel(const int* __restrict__ x)
{
    extern __shared__ char smem_raw[];
    float*   __restrict__ h_sm = (float*)(smem_raw + MAX_ROWS * ROW_B);
    float*   __restrict__ zbuf = (float*)(smem_raw + MAX_ROWS * ROW_B + HID * 4);
    const double2* __restrict__ h2d = (const double2*)h_sm;   // 2x f32x2 per 16B granule
    __shared__ unsigned long long s_cbA, s_cbB;

    const int cta  = blockIdx.x;
    const int tid  = threadIdx.x;
    const int lane = tid & 31;
    const int w    = tid >> 5;

    // unit partition: first 124 CTAs own 14 units, last 24 own 13 (124*14+24*13 = 2048)
    const int nu = (cta < 124) ? 14 : 13;
    const int u0 = (cta < 124) ? cta * 14 : 1736 + (cta - 124) * 13;
    const int nd = nu * 4;                 // valid dot rows (52 or 56)

    // stage weights: per row, first K_SM bf16 into SMEM (row stride ROW_B)
    {
        const char* __restrict__ src = (const char*)(d_Uh + (size_t)u0 * 4 * HID);
        const int n = nd * (ROW_B / 16);
        for (int idx = tid; idx < n; idx += NTHREADS) {
            const int row = idx / (ROW_B / 16);
            const int off = idx % (ROW_B / 16);
            *((uint4*)(smem_raw + (size_t)row * ROW_B) + off) =
                *((const uint4*)(src + (size_t)row * (HID * 2)) + off);
        }
    }
    for (int i = tid; i < HID; i += NTHREADS) h_sm[i] = 0.f;

    // counter bases captured BEFORE the startup barrier (uniform across CTAs)
    unsigned mygen = 0;
    if (tid == 0) {
        s_cbA = *((volatile unsigned long long*)&d_cntA);
        s_cbB = *((volatile unsigned long long*)&d_cntB);
        mygen = *((volatile unsigned*)&d_bargen);
    }
    __syncthreads();
    const unsigned long long cbA = s_cbA;
    const unsigned long long cbB = s_cbB;
    // startup grid barrier (legacy scheme; replay-safe)
    if (tid == 0) {
        __threadfence();
        const unsigned ticket = atomicAdd(&d_barcnt, 1u);
        if (ticket == gridDim.x - 1) {
            d_barcnt = 0;
            __threadfence();
            atomicAdd(&d_bargen, 1u);
        } else {
            unsigned g;
            do {
                asm volatile("ld.acquire.gpu.global.u32 %0, [%1];"
                             : "=r"(g) : "l"(&d_bargen) : "memory");
            } while (g == mygen);
        }
    }
    __syncthreads();

    if (w < 7) {
        // ---------------- compute warps: 8 rows each (r0 = 8w) ----------------
        const int r0 = 8 * w;
        const char* __restrict__ wbase = smem_raw + (size_t)r0 * ROW_B;
        const uint4* __restrict__ tb4 =
            (const uint4*)(d_Uh + ((size_t)(u0 * 4 + r0)) * HID + K_SM);  // 256 uint4/row stride

        float cst = 0.f;   // warp 0 thread u owns unit u's cell state

        // prologue prefetch for t=0
        float4 gz = make_float4(0.f, 0.f, 0.f, 0.f);
        uint4 tw[8];
        if (w == 0 && lane < nu) {
            const int xt = __ldg(&x[0]);
            gz = __ldg(((const float4*)d_G) + (size_t)xt * HID + (u0 + lane));
        }
        #pragma unroll
        for (int rr = 0; rr < 8; rr++) {
            const int off = (r0 + rr < nd) ? rr * 256 : 0;
            tw[rr] = __ldg(tb4 + off + lane);
        }

        for (int t = 0; t < SEQ; t++) {
            unsigned long long a[8];
            #pragma unroll
            for (int rr = 0; rr < 8; rr++) a[rr] = 0ull;

            // dots lower half: k in [0,1024), iters 0-3 (h lower gathered last step)
            #pragma unroll
            for (int ii = 0; ii < 4; ii++) {
                const int ci = lane + (ii << 5);
                const double2 hA = h2d[ci * 2];
                const double2 hB = h2d[ci * 2 + 1];
                const unsigned long long hp0 = __double_as_longlong(hA.x);
                const unsigned long long hp1 = __double_as_longlong(hA.y);
                const unsigned long long hp2 = __double_as_longlong(hB.x);
                const unsigned long long hp3 = __double_as_longlong(hB.y);
                const char* wp = wbase + ci * 16;
                #pragma unroll
                for (int rr = 0; rr < 8; rr++) {
                    const uint4 wv = *(const uint4*)(wp + rr * ROW_B);
                    fma2_bf(wv.x, hp0, a[rr]);
                    fma2_bf(wv.y, hp1, a[rr]);
                    fma2_bf(wv.z, hp2, a[rr]);
                    fma2_bf(wv.w, hp3, a[rr]);
                }
            }

            bar_sync(1, 256);                  // join: warp7 finished upper h gather

            // dots upper half: k in [1024,1792) iters 4-6, + tail [1792,2048)
            #pragma unroll
            for (int ii = 4; ii < 7; ii++) {
                const int ci = lane + (ii << 5);
                const double2 hA = h2d[ci * 2];
                const double2 hB = h2d[ci * 2 + 1];
                const unsigned long long hp0 = __double_as_longlong(hA.x);
                const unsigned long long hp1 = __double_as_longlong(hA.y);
                const unsigned long long hp2 = __double_as_longlong(hB.x);
                const unsigned long long hp3 = __double_as_longlong(hB.y);
                const char* wp = wbase + ci * 16;
                #pragma unroll
                for (int rr = 0; rr < 8; rr++) {
                    const uint4 wv = *(const uint4*)(wp + rr * ROW_B);
                    fma2_bf(wv.x, hp0, a[rr]);
                    fma2_bf(wv.y, hp1, a[rr]);
                    fma2_bf(wv.z, hp2, a[rr]);
                    fma2_bf(wv.w, hp3, a[rr]);
                }
            }
            {   // tail: k = K_SM + lane*8 (prefetched from L2)
                const int ci = (K_SM >> 3) + lane;
                const double2 hA = h2d[ci * 2];
                const double2 hB = h2d[ci * 2 + 1];
                const unsigned long long hp0 = __double_as_longlong(hA.x);
                const unsigned long long hp1 = __double_as_longlong(hA.y);
                const unsigned long long hp2 = __double_as_longlong(hB.x);
                const unsigned long long hp3 = __double_as_longlong(hB.y);
                #pragma unroll
                for (int rr = 0; rr < 8; rr++) {
                    fma2_bf(tw[rr].x, hp0, a[rr]);
                    fma2_bf(tw[rr].y, hp1, a[rr]);
                    fma2_bf(tw[rr].z, hp2, a[rr]);
                    fma2_bf(tw[rr].w, hp3, a[rr]);
                }
            }

            // warp-reduce each row; row owner lane writes z to SMEM
            float zv[8];
            #pragma unroll
            for (int rr = 0; rr < 8; rr++) zv[rr] = acc2_sum(a[rr]);
            #pragma unroll
            for (int rr = 0; rr < 8; rr++) {
                #pragma unroll
                for (int off = 16; off > 0; off >>= 1)
                    zv[rr] += __shfl_xor_sync(0xffffffffu, zv[rr], off);
            }
            #pragma unroll
            for (int rr = 0; rr < 8; rr++)
                if (lane == rr) zbuf[r0 + rr] = zv[rr];
            bar_sync(2, 224);                  // zbuf complete (compute warps only)

            // warp 0: gates + cell update + publish
            if (w == 0 && lane < nu) {
                const float4 zz = *(const float4*)&zbuf[4 * lane];
                const float ig = sigmoid_f(zz.x + gz.x);
                const float fg = sigmoid_f(zz.y + gz.y);
                const float gg = tanh_f   (zz.z + gz.z);
                const float og = sigmoid_f(zz.w + gz.w);
                const float cn = fg * cst + ig * gg;
                cst = cn;
                const float hn = og * tanh_f(cn);
                const int j = u0 + lane;
                __stcg(&d_hbuf[t & 1][j], hn);
                d_hs[(size_t)t * HID + j] = hn;
                if (t == SEQ - 1) d_cfinal[j] = cn;
            }

            if (t == SEQ - 1) break;           // warp7 breaks too; no more bars

            // arrival: release after warp-wide publish (syncwarp orders lanes' stores)
            if (w == 0) {
                __syncwarp();
                if (lane == 0)
                    red_add_release((cta < NGRP) ? &d_cntA : &d_cntB);
            }

            // prefetch for t+1 (flies while warp7 finishes counterA detect + gather)
            if (w == 0 && lane < nu) {
                const int xt = __ldg(&x[t + 1]);
                gz = __ldg(((const float4*)d_G) + (size_t)xt * HID + (u0 + lane));
            }
            #pragma unroll
            for (int rr = 0; rr < 8; rr++) {
                const int off = (r0 + rr < nd) ? rr * 256 : 0;
                tw[rr] = __ldg(tb4 + off + lane);
            }

            bar_sync(1, 256);                  // join: warp7 gathered lower h(t)
        }
    } else {
        // ---------------- warp 7: sync + gather warp ----------------
        for (int t = 0; t < SEQ; t++) {
            // wait for upper-half publishers of h(t-1), gather upper 4KB
            if (t > 0) {
                if (lane == 0) {
                    const unsigned long long tgt = cbB + (unsigned long long)t * NGRP;
                    while (ld_acq64(&d_cntB) < tgt) { }
                }
                __syncwarp();
                const float4* __restrict__ s4 = (const float4*)d_hbuf[(t - 1) & 1];
                float4* __restrict__ dst4 = (float4*)h_sm;
                #pragma unroll
                for (int k = 0; k < 8; k++)
                    dst4[256 + lane + k * 32] = __ldcg(&s4[256 + lane + k * 32]);
            }
            bar_sync(1, 256);                  // release upper h(t-1) to compute warps

            if (t == SEQ - 1) break;

            // wait for lower-half publishers of h(t), gather lower 4KB
            if (lane == 0) {
                const unsigned long long tgt = cbA + (unsigned long long)(t + 1) * NGRP;
                while (ld_acq64(&d_cntA) < tgt) { }
            }
            __syncwarp();
            {
                const float4* __restrict__ s4 = (const float4*)d_hbuf[t & 1];
                float4* __restrict__ dst4 = (float4*)h_sm;
                #pragma unroll
                for (int k = 0; k < 8; k++)
                    dst4[lane + k * 32] = __ldcg(&s4[lane + k * 32]);
            }
            bar_sync(1, 256);                  // end-of-step join
        }
    }
}

// ============================================================================
// Kernel 4: out = hs @ V_w + V_b   (8192x2048 @ 2048x256)
// ============================================================================
__global__ void __launch_bounds__(256) out_gemm_kernel(const float* __restrict__ Vw,
                                                       const float* __restrict__ Vb,
                                                       float* __restrict__ out)
{
    __shared__ float As[16][64];
    __shared__ float Bs[16][64];
    const int tid = threadIdx.x;
    const int tx = tid & 15, ty = tid >> 4;
    const int m0 = blockIdx.x * 64, n0 = blockIdx.y * 64;

    float acc[4][4];
    #pragma unroll
    for (int i = 0; i < 4; i++)
        #pragma unroll
        for (int j = 0; j < 4; j++) acc[i][j] = 0.f;

    const int ar = tid >> 2, ac = (tid & 3) * 4;
    const int br = tid >> 4, bc = (tid & 15) * 4;

    for (int k0 = 0; k0 < HID; k0 += 16) {
        const float4 av = *(const float4*)&d_hs[(size_t)(m0 + ar) * HID + k0 + ac];
        As[ac + 0][ar] = av.x; As[ac + 1][ar] = av.y;
        As[ac + 2][ar] = av.z; As[ac + 3][ar] = av.w;
        *(float4*)&Bs[br][bc] = *(const float4*)&Vw[(size_t)(k0 + br) * OUTN + n0 + bc];
        __syncthreads();
        #pragma unroll
        for (int kk = 0; kk < 16; kk++) {
            float a4[4], b4[4];
            *(float4*)a4 = *(const float4*)&As[kk][ty * 4];
            *(float4*)b4 = *(const float4*)&Bs[kk][tx * 4];
            #pragma unroll
            for (int i = 0; i < 4; i++)
                #pragma unroll
                for (int j = 0; j < 4; j++)
                    acc[i][j] = fmaf(a4[i], b4[j], acc[i][j]);
        }
        __syncthreads();
    }
    #pragma unroll
    for (int i = 0; i < 4; i++) {
        #pragma unroll
        for (int j = 0; j < 4; j++) {
            const int oo = n0 + tx * 4 + j;
            out[(size_t)(m0 + ty * 4 + i) * OUTN + oo] = acc[i][j] + Vb[oo];
        }
    }
}

// ============================================================================
// Kernel 5: optional tail (h_T, c_T) if harness expects them appended
// ============================================================================
__global__ void tail_copy_kernel(float* __restrict__ out)
{
    const int i = blockIdx.x * blockDim.x + threadIdx.x;
    if (i < HID) {
        out[(size_t)SEQ * OUTN + i]       = d_hs[(size_t)(SEQ - 1) * HID + i];
        out[(size_t)SEQ * OUTN + HID + i] = d_cfinal[i];
    }
}

// ============================================================================
// host launcher
// inputs: 0:x 1:emb 2:W_i 3:b_i 4:U_i 5:c_i 6:W_f 7:b_f 8:U_f 9:c_f
//         10:W_g 11:b_g 12:U_g 13:c_g 14:W_o 15:b_o 16:U_o 17:c_o 18:V_w 19:V_b
// ============================================================================
extern "C" void kernel_launch(void* const* d_in, const int* in_sizes, int n_in,
                              void* d_out, int out_size)
{
    const int*   x   = (const int*)d_in[0];
    const float* emb = (const float*)d_in[1];

    GateArgs ga;
    UArgs ua;
    ga.W[0] = (const float*)d_in[2];  ga.b[0] = (const float*)d_in[3];
    ua.U[0] = (const float*)d_in[4];  ga.cb[0] = (const float*)d_in[5];
    ga.W[1] = (const float*)d_in[6];  ga.b[1] = (const float*)d_in[7];
    ua.U[1] = (const float*)d_in[8];  ga.cb[1] = (const float*)d_in[9];
    ga.W[2] = (const float*)d_in[10]; ga.b[2] = (const float*)d_in[11];
    ua.U[2] = (const float*)d_in[12]; ga.cb[2] = (const float*)d_in[13];
    ga.W[3] = (const float*)d_in[14]; ga.b[3] = (const float*)d_in[15];
    ua.U[3] = (const float*)d_in[16]; ga.cb[3] = (const float*)d_in[17];
    const float* Vw = (const float*)d_in[18];
    const float* Vb = (const float*)d_in[19];
    float* out = (float*)d_out;

    cudaFuncSetAttribute(lstm_recur_kernel,
                         cudaFuncAttributeMaxDynamicSharedMemorySize, SMEM_RECUR);

    prep_tables_kernel<<<dim3(VOCAB / 8, 4), 256>>>(emb, ga);
    prep_weights_kernel<<<dim3(HID / 32, HID / 32, 4), dim3(32, 32)>>>(ua);
    nop_kernel<<<1, 32>>>();
    lstm_recur_kernel<<<NCTA, NTHREADS, SMEM_RECUR>>>(x);   // ncu -s 5 target (as in R10)
    out_gemm_kernel<<<dim3(SEQ / 64, OUTN / 64), 256>>>(Vw, Vb, out);
    if (out_size >= SEQ * OUTN + 2 * HID)
        tail_copy_kernel<<<(HID + 255) / 256, 256>>>(out);
}

// round 16
// speedup vs baseline: 1.0688x; 1.0688x over previous
#include <cuda_runtime.h>
#include <cuda_bf16.h>
#include <cstdint>

#define SEQ    8192
#define VOCAB  256
#define HID    2048
#define OUTN   256

#define NCTA     148
#define NTHREADS 256          // 8 warps, 7 dot-rows each
#define K_SM     1792         // k<1792 in SMEM (224 uint4/row); k in [1792,2048) via prefetched L2 tail
#define ROW_B    (K_SM * 2)   // 3584 bytes per SMEM weight row
#define MAX_ROWS 56
// weights 200704 + h 8192 + zbuf 256 = 209152 <= 232448
#define SMEM_RECUR (MAX_ROWS * ROW_B + HID * 4 + 64 * 4)

// ---------------- device scratch (module-scope: no runtime allocs) ----------------
__device__ __nv_bfloat16 d_Uh[(size_t)4 * HID * HID]; // [(j*4+g)*HID + k] = bf16(U_g[k][j])
__device__ float  d_G[(size_t)4 * VOCAB * HID];       // [(v*HID + j)*4 + g] = emb[v]@W_g + b_g + c_g
__device__ float  d_hs[(size_t)SEQ * HID];            // h history for output GEMM
__device__ float  d_hbuf[2][HID];                     // double-buffered cross-CTA h
__device__ float  d_cfinal[HID];
__device__ unsigned d_barcnt;                         // startup barrier (legacy, replay-safe)
__device__ unsigned d_bargen;
__device__ unsigned long long d_stepcnt;              // monotonic step-barrier counter

struct GateArgs {
    const float* W[4];
    const float* b[4];
    const float* cb[4];
};
struct UArgs {
    const float* U[4];
};

// packed bf16x2 -> f32x2 expand + packed FMA: acc(f32x2) += h(f32x2) * expand(w)
__device__ __forceinline__ void fma2_bf(unsigned w, unsigned long long hp,
                                        unsigned long long& acc)
{
    asm("{\n\t"
        ".reg .b32 lo, hi;\n\t"
        ".reg .b64 wp;\n\t"
        "shl.b32 lo, %1, 16;\n\t"
        "and.b32 hi, %1, 0xffff0000;\n\t"
        "mov.b64 wp, {lo, hi};\n\t"
        "fma.rn.f32x2 %0, %2, wp, %0;\n\t"
        "}" : "+l"(acc) : "r"(w), "l"(hp));
}
__device__ __forceinline__ float acc2_sum(unsigned long long a)
{
    return __uint_as_float((unsigned)a) + __uint_as_float((unsigned)(a >> 32));
}

__device__ __forceinline__ void red_add_release(unsigned long long* p)
{
    asm volatile("red.release.gpu.global.add.u64 [%0], 1;" :: "l"(p) : "memory");
}
__device__ __forceinline__ unsigned long long ld_acq64(const unsigned long long* p)
{
    unsigned long long v;
    asm volatile("ld.acquire.gpu.global.u64 %0, [%1];" : "=l"(v) : "l"(p) : "memory");
    return v;
}

// ============================================================================
// Kernel 1: gate tables  G[v][j][g] = sum_k emb[v][k]*W_g[k][j] + b_g[j] + c_g[j]
// ============================================================================
__global__ void __launch_bounds__(256) prep_tables_kernel(const float* __restrict__ emb, GateArgs ga)
{
    const int g  = blockIdx.y;
    const float* __restrict__ W  = ga.W[g];
    const float* __restrict__ b  = ga.b[g];
    const float* __restrict__ cb = ga.cb[g];
    const int v0 = blockIdx.x * 8;
    const int tid = threadIdx.x;

    __shared__ float es[8 * 256];
    for (int i = tid; i < 8 * 256; i += 256)
        es[i] = emb[(size_t)(v0 + (i >> 8)) * VOCAB + (i & 255)];
    __syncthreads();

    for (int jj = 0; jj < 8; jj++) {
        const int j = tid + (jj << 8);
        float acc[8];
        #pragma unroll
        for (int v = 0; v < 8; v++) acc[v] = 0.f;
        #pragma unroll 4
        for (int k = 0; k < 256; k++) {
            const float wv = W[(size_t)k * HID + j];
            #pragma unroll
            for (int v = 0; v < 8; v++)
                acc[v] = fmaf(es[(v << 8) + k], wv, acc[v]);
        }
        const float bias = b[j] + cb[j];
        #pragma unroll
        for (int v = 0; v < 8; v++)
            d_G[(((size_t)(v0 + v) * HID) + j) * 4 + g] = acc[v] + bias;
    }
}

// ============================================================================
// Kernel 2: transpose + bf16-convert U:  d_Uh[(j*4+g)*HID + k] = bf16(U_g[k][j])
// ============================================================================
__global__ void __launch_bounds__(1024) prep_weights_kernel(UArgs ua)
{
    const int g = blockIdx.z;
    const float* __restrict__ U = ua.U[g];
    __shared__ float tile[32][33];
    const int j0 = blockIdx.x * 32;
    const int k0 = blockIdx.y * 32;
    const int tx = threadIdx.x, ty = threadIdx.y;

    tile[ty][tx] = U[(size_t)(k0 + ty) * HID + (j0 + tx)];
    __syncthreads();
    d_Uh[((size_t)(j0 + ty) * 4 + g) * HID + (k0 + tx)] = __float2bfloat16(tile[tx][ty]);
}

// no-op alignment kernel (keeps lstm_recur at ncu launch index 5)
__global__ void nop_kernel() {}

// ============================================================================
// Kernel 3: persistent recurrence. 148 CTAs (1/SM), 8 warps x 7 dot-rows.
// ============================================================================
__device__ __forceinline__ float sigmoid_f(float z)
{
    return 1.f / (1.f + __expf(-z));
}
__device__ __forceinline__ float tanh_f(float z)
{
    const float e = __expf(2.f * z);
    return 1.f - __fdividef(2.f, 1.f + e);
}

__global__ void __launch_bounds__(NTHREADS, 1) lstm_recur_kernel(const int* __restrict__ x)
{
    extern __shared__ char smem_raw[];
    float*   __restrict__ h_sm = (float*)(smem_raw + MAX_ROWS * ROW_B);
    float*   __restrict__ zbuf = (float*)(smem_raw + MAX_ROWS * ROW_B + HID * 4);
    const double2* __restrict__ h2d = (const double2*)h_sm;   // 2x f32x2 per 16B granule

    const int cta  = blockIdx.x;
    const int tid  = threadIdx.x;
    const int lane = tid & 31;
    const int w    = tid >> 5;

    // unit partition: first 124 CTAs own 14 units, last 24 own 13 (124*14+24*13 = 2048)
    const int nu = (cta < 124) ? 14 : 13;
    const int u0 = (cta < 124) ? cta * 14 : 1736 + (cta - 124) * 13;
    const int nd = nu * 4;                 // valid dot rows (52 or 56)

    // stage weights: per row, first K_SM bf16 into SMEM (row stride ROW_B)
    {
        const char* __restrict__ src = (const char*)(d_Uh + (size_t)u0 * 4 * HID);
        const int n = nd * (ROW_B / 16);
        for (int idx = tid; idx < n; idx += NTHREADS) {
            const int row = idx / (ROW_B / 16);
            const int off = idx % (ROW_B / 16);
            *((uint4*)(smem_raw + (size_t)row * ROW_B) + off) =
                *((const uint4*)(src + (size_t)row * (HID * 2)) + off);
        }
    }
    for (int i = tid; i < HID; i += NTHREADS) h_sm[i] = 0.f;

    // warp w owns local rows [7w, 7w+7)
    const int r0 = 7 * w;
    const char* __restrict__ wbase = smem_raw + (size_t)r0 * ROW_B;
    const uint4* __restrict__ tb4 =
        (const uint4*)(d_Uh + ((size_t)(u0 * 4 + r0)) * HID + K_SM);  // tail base, 256 uint4/row stride

    // capture monotonic-counter base BEFORE the startup barrier
    unsigned long long cbase = 0ull;
    unsigned mygen = 0;
    if (tid == 0) {
        cbase = *((volatile unsigned long long*)&d_stepcnt);
        mygen = *((volatile unsigned*)&d_bargen);
    }
    __syncthreads();
    // startup grid barrier (legacy scheme; replay-safe)
    if (tid == 0) {
        __threadfence();
        const unsigned ticket = atomicAdd(&d_barcnt, 1u);
        if (ticket == gridDim.x - 1) {
            d_barcnt = 0;
            __threadfence();
            atomicAdd(&d_bargen, 1u);
        } else {
            unsigned g;
            do {
                asm volatile("ld.acquire.gpu.global.u32 %0, [%1];"
                             : "=r"(g) : "l"(&d_bargen) : "memory");
            } while (g == mygen);
        }
    }
    __syncthreads();

    float cst = 0.f;   // cell state: warp 0 thread u owns unit u

    for (int t = 0; t < SEQ; t++) {
        // prefetch gate-table row + weight tails via ld.global.cg (L2-resident,
        // no L1, NO streaming hint -> the 4MB tail set stays in L2 across steps)
        float4 gz = make_float4(0.f, 0.f, 0.f, 0.f);
        uint4 tw[7];
        if (w == 0 && lane < nu) {
            const int xt = __ldcg(&x[t]);
            gz = __ldcg(((const float4*)d_G) + (size_t)xt * HID + (u0 + lane));
        }
        #pragma unroll
        for (int rr = 0; rr < 7; rr++) {
            const int off = (r0 + rr < nd) ? rr * 256 : 0;   // clamp invalid rows (stay in-bounds)
            tw[rr] = __ldcg(tb4 + off + lane);
        }

        // dots: 7 SMEM iters (uint4 weights = 16 k-elems each) + 1 L2-tail iter
        unsigned long long a[7];
        #pragma unroll
        for (int rr = 0; rr < 7; rr++) a[rr] = 0ull;

        #pragma unroll 2
        for (int ii = 0; ii < 7; ii++) {
            const int ci = lane + (ii << 5);            // uint4 column index (k = 8*ci)
            const double2 hA = h2d[ci * 2];
            const double2 hB = h2d[ci * 2 + 1];
            const unsigned long long hp0 = __double_as_longlong(hA.x);
            const unsigned long long hp1 = __double_as_longlong(hA.y);
            const unsigned long long hp2 = __double_as_longlong(hB.x);
            const unsigned long long hp3 = __double_as_longlong(hB.y);
            const char* wp = wbase + ci * 16;
            #pragma unroll
            for (int rr = 0; rr < 7; rr++) {
                const uint4 wv = *(const uint4*)(wp + rr * ROW_B);
                fma2_bf(wv.x, hp0, a[rr]);
                fma2_bf(wv.y, hp1, a[rr]);
                fma2_bf(wv.z, hp2, a[rr]);
                fma2_bf(wv.w, hp3, a[rr]);
            }
        }
        {   // tail: k = K_SM + lane*8 (prefetched)
            const int ci = (K_SM >> 3) + lane;
            const double2 hA = h2d[ci * 2];
            const double2 hB = h2d[ci * 2 + 1];
            const unsigned long long hp0 = __double_as_longlong(hA.x);
            const unsigned long long hp1 = __double_as_longlong(hA.y);
            const unsigned long long hp2 = __double_as_longlong(hB.x);
            const unsigned long long hp3 = __double_as_longlong(hB.y);
            #pragma unroll
            for (int rr = 0; rr < 7; rr++) {
                fma2_bf(tw[rr].x, hp0, a[rr]);
                fma2_bf(tw[rr].y, hp1, a[rr]);
                fma2_bf(tw[rr].z, hp2, a[rr]);
                fma2_bf(tw[rr].w, hp3, a[rr]);
            }
        }

        // warp-reduce each row; row owner lane writes z to SMEM
        float zv[7];
        #pragma unroll
        for (int rr = 0; rr < 7; rr++) zv[rr] = acc2_sum(a[rr]);
        #pragma unroll
        for (int rr = 0; rr < 7; rr++) {
            #pragma unroll
            for (int off = 16; off > 0; off >>= 1)
                zv[rr] += __shfl_xor_sync(0xffffffffu, zv[rr], off);
        }
        #pragma unroll
        for (int rr = 0; rr < 7; rr++)
            if (lane == rr) zbuf[r0 + rr] = zv[rr];
        __syncthreads();                       // all dots done; zbuf complete; h_sm reads finished

        // warp 0: gates + cell update + publish (st.cg)
        if (w == 0 && lane < nu) {
            const float4 zz = *(const float4*)&zbuf[4 * lane];
            const float ig = sigmoid_f(zz.x + gz.x);
            const float fg = sigmoid_f(zz.y + gz.y);
            const float gg = tanh_f   (zz.z + gz.z);
            const float og = sigmoid_f(zz.w + gz.w);
            const float cn = fg * cst + ig * gg;
            cst = cn;
            const float hn = og * tanh_f(cn);
            const int j = u0 + lane;
            __stcg(&d_hbuf[t & 1][j], hn);
            d_hs[(size_t)t * HID + j] = hn;
            if (t == SEQ - 1) d_cfinal[j] = cn;
        }

        if (t == SEQ - 1) break;               // no more cross-CTA exchange needed

        // grid barrier: fire-and-forget release arrival, acquire poll on monotonic counter
        __syncthreads();                       // h stores done CTA-wide
        if (tid == 0) {
            red_add_release(&d_stepcnt);
            const unsigned long long target = cbase + (unsigned long long)(t + 1) * (unsigned)gridDim.x;
            while (ld_acq64(&d_stepcnt) < target) { }
        }
        __syncthreads();                       // barrier observed CTA-wide

        // gather the full new h into SMEM (L2, bypass L1): 2 float4 per thread
        {
            float4* __restrict__ dst4 = (float4*)h_sm;
            const float4* __restrict__ s4 = (const float4*)d_hbuf[t & 1];
            #pragma unroll
            for (int kk = 0; kk < 2; kk++)
                dst4[tid + kk * NTHREADS] = __ldcg(&s4[tid + kk * NTHREADS]);
        }
        __syncthreads();                       // h(t) fully in SMEM for next dots
    }
}

// ============================================================================
// Kernel 4: out = hs @ V_w + V_b   (8192x2048 @ 2048x256)
// ============================================================================
__global__ void __launch_bounds__(256) out_gemm_kernel(const float* __restrict__ Vw,
                                                       const float* __restrict__ Vb,
                                                       float* __restrict__ out)
{
    __shared__ float As[16][64];
    __shared__ float Bs[16][64];
    const int tid = threadIdx.x;
    const int tx = tid & 15, ty = tid >> 4;
    const int m0 = blockIdx.x * 64, n0 = blockIdx.y * 64;

    float acc[4][4];
    #pragma unroll
    for (int i = 0; i < 4; i++)
        #pragma unroll
        for (int j = 0; j < 4; j++) acc[i][j] = 0.f;

    const int ar = tid >> 2, ac = (tid & 3) * 4;
    const int br = tid >> 4, bc = (tid & 15) * 4;

    for (int k0 = 0; k0 < HID; k0 += 16) {
        const float4 av = *(const float4*)&d_hs[(size_t)(m0 + ar) * HID + k0 + ac];
        As[ac + 0][ar] = av.x; As[ac + 1][ar] = av.y;
        As[ac + 2][ar] = av.z; As[ac + 3][ar] = av.w;
        *(float4*)&Bs[br][bc] = *(const float4*)&Vw[(size_t)(k0 + br) * OUTN + n0 + bc];
        __syncthreads();
        #pragma unroll
        for (int kk = 0; kk < 16; kk++) {
            float a4[4], b4[4];
            *(float4*)a4 = *(const float4*)&As[kk][ty * 4];
            *(float4*)b4 = *(const float4*)&Bs[kk][tx * 4];
            #pragma unroll
            for (int i = 0; i < 4; i++)
                #pragma unroll
                for (int j = 0; j < 4; j++)
                    acc[i][j] = fmaf(a4[i], b4[j], acc[i][j]);
        }
        __syncthreads();
    }
    #pragma unroll
    for (int i = 0; i < 4; i++) {
        #pragma unroll
        for (int j = 0; j < 4; j++) {
            const int oo = n0 + tx * 4 + j;
            out[(size_t)(m0 + ty * 4 + i) * OUTN + oo] = acc[i][j] + Vb[oo];
        }
    }
}

// ============================================================================
// Kernel 5: optional tail (h_T, c_T) if harness expects them appended
// ============================================================================
__global__ void tail_copy_kernel(float* __restrict__ out)
{
    const int i = blockIdx.x * blockDim.x + threadIdx.x;
    if (i < HID) {
        out[(size_t)SEQ * OUTN + i]       = d_hs[(size_t)(SEQ - 1) * HID + i];
        out[(size_t)SEQ * OUTN + HID + i] = d_cfinal[i];
    }
}

// ============================================================================
// host launcher
// inputs: 0:x 1:emb 2:W_i 3:b_i 4:U_i 5:c_i 6:W_f 7:b_f 8:U_f 9:c_f
//         10:W_g 11:b_g 12:U_g 13:c_g 14:W_o 15:b_o 16:U_o 17:c_o 18:V_w 19:V_b
// ============================================================================
extern "C" void kernel_launch(void* const* d_in, const int* in_sizes, int n_in,
                              void* d_out, int out_size)
{
    const int*   x   = (const int*)d_in[0];
    const float* emb = (const float*)d_in[1];

    GateArgs ga;
    UArgs ua;
    ga.W[0] = (const float*)d_in[2];  ga.b[0] = (const float*)d_in[3];
    ua.U[0] = (const float*)d_in[4];  ga.cb[0] = (const float*)d_in[5];
    ga.W[1] = (const float*)d_in[6];  ga.b[1] = (const float*)d_in[7];
    ua.U[1] = (const float*)d_in[8];  ga.cb[1] = (const float*)d_in[9];
    ga.W[2] = (const float*)d_in[10]; ga.b[2] = (const float*)d_in[11];
    ua.U[2] = (const float*)d_in[12]; ga.cb[2] = (const float*)d_in[13];
    ga.W[3] = (const float*)d_in[14]; ga.b[3] = (const float*)d_in[15];
    ua.U[3] = (const float*)d_in[16]; ga.cb[3] = (const float*)d_in[17];
    const float* Vw = (const float*)d_in[18];
    const float* Vb = (const float*)d_in[19];
    float* out = (float*)d_out;

    cudaFuncSetAttribute(lstm_recur_kernel,
                         cudaFuncAttributeMaxDynamicSharedMemorySize, SMEM_RECUR);

    prep_tables_kernel<<<dim3(VOCAB / 8, 4), 256>>>(emb, ga);
    prep_weights_kernel<<<dim3(HID / 32, HID / 32, 4), dim3(32, 32)>>>(ua);
    nop_kernel<<<1, 32>>>();
    lstm_recur_kernel<<<NCTA, NTHREADS, SMEM_RECUR>>>(x);   // ncu -s 5 target
    out_gemm_kernel<<<dim3(SEQ / 64, OUTN / 64), 256>>>(Vw, Vb, out);
    if (out_size >= SEQ * OUTN + 2 * HID)
        tail_copy_kernel<<<(HID + 255) / 256, 256>>>(out);
}

// round 17
// speedup vs baseline: 1.0766x; 1.0073x over previous
#include <cuda_runtime.h>
#include <cuda_bf16.h>
#include <cstdint>

#define SEQ    8192
#define VOCAB  256
#define HID    2048
#define OUTN   256

#define NCTA     148
#define NTHREADS 256          // 8 warps, 7 dot-rows each
#define K_SM     1792         // k<1792 in SMEM (224 uint4/row); k in [1792,2048) via prefetched L2 tail
#define ROW_B    (K_SM * 2)   // 3584 bytes per SMEM weight row
#define MAX_ROWS 56
// weights 200704 + h 8192 + zbuf 256 = 209152 <= 232448
#define SMEM_RECUR (MAX_ROWS * ROW_B + HID * 4 + 64 * 4)

// ---------------- device scratch (module-scope: no runtime allocs) ----------------
__device__ __nv_bfloat16 d_Uh[(size_t)4 * HID * HID]; // [(j*4+g)*HID + k] = bf16(U_g[k][j])
__device__ float  d_G[(size_t)4 * VOCAB * HID];       // [(v*HID + j)*4 + g] = emb[v]@W_g + b_g + c_g
__device__ float  d_hs[(size_t)SEQ * HID];            // h history for output GEMM
__device__ float  d_hbuf[2][HID];                     // double-buffered cross-CTA h
__device__ float  d_cfinal[HID];
__device__ unsigned d_barcnt;                         // startup barrier (legacy, replay-safe)
__device__ unsigned d_bargen;
__device__ unsigned long long d_stepcnt;              // monotonic step-barrier counter

struct GateArgs {
    const float* W[4];
    const float* b[4];
    const float* cb[4];
};
struct UArgs {
    const float* U[4];
};

// packed bf16x2 -> f32x2 expand + packed FMA: acc(f32x2) += h(f32x2) * expand(w)
__device__ __forceinline__ void fma2_bf(unsigned w, unsigned long long hp,
                                        unsigned long long& acc)
{
    asm("{\n\t"
        ".reg .b32 lo, hi;\n\t"
        ".reg .b64 wp;\n\t"
        "shl.b32 lo, %1, 16;\n\t"
        "and.b32 hi, %1, 0xffff0000;\n\t"
        "mov.b64 wp, {lo, hi};\n\t"
        "fma.rn.f32x2 %0, %2, wp, %0;\n\t"
        "}" : "+l"(acc) : "r"(w), "l"(hp));
}
__device__ __forceinline__ float acc2_sum(unsigned long long a)
{
    return __uint_as_float((unsigned)a) + __uint_as_float((unsigned)(a >> 32));
}

__device__ __forceinline__ void red_add_release(unsigned long long* p)
{
    asm volatile("red.release.gpu.global.add.u64 [%0], 1;" :: "l"(p) : "memory");
}
__device__ __forceinline__ unsigned long long ld_acq64(const unsigned long long* p)
{
    unsigned long long v;
    asm volatile("ld.acquire.gpu.global.u64 %0, [%1];" : "=l"(v) : "l"(p) : "memory");
    return v;
}

// ============================================================================
// Kernel 1: gate tables  G[v][j][g] = sum_k emb[v][k]*W_g[k][j] + b_g[j] + c_g[j]
// ============================================================================
__global__ void __launch_bounds__(256) prep_tables_kernel(const float* __restrict__ emb, GateArgs ga)
{
    const int g  = blockIdx.y;
    const float* __restrict__ W  = ga.W[g];
    const float* __restrict__ b  = ga.b[g];
    const float* __restrict__ cb = ga.cb[g];
    const int v0 = blockIdx.x * 8;
    const int tid = threadIdx.x;

    __shared__ float es[8 * 256];
    for (int i = tid; i < 8 * 256; i += 256)
        es[i] = emb[(size_t)(v0 + (i >> 8)) * VOCAB + (i & 255)];
    __syncthreads();

    for (int jj = 0; jj < 8; jj++) {
        const int j = tid + (jj << 8);
        float acc[8];
        #pragma unroll
        for (int v = 0; v < 8; v++) acc[v] = 0.f;
        #pragma unroll 4
        for (int k = 0; k < 256; k++) {
            const float wv = W[(size_t)k * HID + j];
            #pragma unroll
            for (int v = 0; v < 8; v++)
                acc[v] = fmaf(es[(v << 8) + k], wv, acc[v]);
        }
        const float bias = b[j] + cb[j];
        #pragma unroll
        for (int v = 0; v < 8; v++)
            d_G[(((size_t)(v0 + v) * HID) + j) * 4 + g] = acc[v] + bias;
    }
}

// ============================================================================
// Kernel 2: transpose + bf16-convert U:  d_Uh[(j*4+g)*HID + k] = bf16(U_g[k][j])
// ============================================================================
__global__ void __launch_bounds__(1024) prep_weights_kernel(UArgs ua)
{
    const int g = blockIdx.z;
    const float* __restrict__ U = ua.U[g];
    __shared__ float tile[32][33];
    const int j0 = blockIdx.x * 32;
    const int k0 = blockIdx.y * 32;
    const int tx = threadIdx.x, ty = threadIdx.y;

    tile[ty][tx] = U[(size_t)(k0 + ty) * HID + (j0 + tx)];
    __syncthreads();
    d_Uh[((size_t)(j0 + ty) * 4 + g) * HID + (k0 + tx)] = __float2bfloat16(tile[tx][ty]);
}

// no-op alignment kernel (keeps lstm_recur at ncu launch index 5)
__global__ void nop_kernel() {}

// ============================================================================
// Kernel 3: persistent recurrence. 148 CTAs (1/SM), 8 warps x 7 dot-rows.
// ============================================================================
__device__ __forceinline__ float sigmoid_f(float z)
{
    return 1.f / (1.f + __expf(-z));
}
__device__ __forceinline__ float tanh_f(float z)
{
    const float e = __expf(2.f * z);
    return 1.f - __fdividef(2.f, 1.f + e);
}

__global__ void __launch_bounds__(NTHREADS, 1) lstm_recur_kernel(const int* __restrict__ x)
{
    extern __shared__ char smem_raw[];
    float*   __restrict__ h_sm = (float*)(smem_raw + MAX_ROWS * ROW_B);
    float*   __restrict__ zbuf = (float*)(smem_raw + MAX_ROWS * ROW_B + HID * 4);
    const double2* __restrict__ h2d = (const double2*)h_sm;   // 2x f32x2 per 16B granule

    const int cta  = blockIdx.x;
    const int tid  = threadIdx.x;
    const int lane = tid & 31;
    const int w    = tid >> 5;

    // unit partition: first 124 CTAs own 14 units, last 24 own 13 (124*14+24*13 = 2048)
    const int nu = (cta < 124) ? 14 : 13;
    const int u0 = (cta < 124) ? cta * 14 : 1736 + (cta - 124) * 13;
    const int nd = nu * 4;                 // valid dot rows (52 or 56)

    // stage weights: per row, first K_SM bf16 into SMEM (row stride ROW_B)
    {
        const char* __restrict__ src = (const char*)(d_Uh + (size_t)u0 * 4 * HID);
        const int n = nd * (ROW_B / 16);
        for (int idx = tid; idx < n; idx += NTHREADS) {
            const int row = idx / (ROW_B / 16);
            const int off = idx % (ROW_B / 16);
            *((uint4*)(smem_raw + (size_t)row * ROW_B) + off) =
                *((const uint4*)(src + (size_t)row * (HID * 2)) + off);
        }
    }
    for (int i = tid; i < HID; i += NTHREADS) h_sm[i] = 0.f;

    // warp w owns local rows [7w, 7w+7)
    const int r0 = 7 * w;
    const char* __restrict__ wbase = smem_raw + (size_t)r0 * ROW_B;
    const uint4* __restrict__ tb4 =
        (const uint4*)(d_Uh + ((size_t)(u0 * 4 + r0)) * HID + K_SM);  // tail base, 256 uint4/row stride

    // capture monotonic-counter base BEFORE the startup barrier
    unsigned long long cbase = 0ull;
    unsigned mygen = 0;
    if (tid == 0) {
        cbase = *((volatile unsigned long long*)&d_stepcnt);
        mygen = *((volatile unsigned*)&d_bargen);
    }
    __syncthreads();
    // startup grid barrier (legacy scheme; replay-safe)
    if (tid == 0) {
        __threadfence();
        const unsigned ticket = atomicAdd(&d_barcnt, 1u);
        if (ticket == gridDim.x - 1) {
            d_barcnt = 0;
            __threadfence();
            atomicAdd(&d_bargen, 1u);
        } else {
            unsigned g;
            do {
                asm volatile("ld.acquire.gpu.global.u32 %0, [%1];"
                             : "=r"(g) : "l"(&d_bargen) : "memory");
            } while (g == mygen);
        }
    }
    __syncthreads();

    float cst = 0.f;   // cell state: warp 0 thread u owns unit u

    for (int t = 0; t < SEQ; t++) {
        // prefetch gate-table row + weight tails via ld.global.cg (L2-resident, no L1)
        float4 gz = make_float4(0.f, 0.f, 0.f, 0.f);
        uint4 tw[7];
        if (w == 0 && lane < nu) {
            const int xt = __ldcg(&x[t]);
            gz = __ldcg(((const float4*)d_G) + (size_t)xt * HID + (u0 + lane));
        }
        #pragma unroll
        for (int rr = 0; rr < 7; rr++) {
            const int off = (r0 + rr < nd) ? rr * 256 : 0;   // clamp invalid rows (stay in-bounds)
            tw[rr] = __ldcg(tb4 + off + lane);
        }

        // dots: 7 SMEM iters (uint4 weights = 16 k-elems each) + 1 L2-tail iter.
        // FULL unroll: ptxas front-batches the LDS stream + register double-buffers,
        // hiding the 29-cyc LDS latency at only 2 warps/SMSP.
        unsigned long long a[7];
        #pragma unroll
        for (int rr = 0; rr < 7; rr++) a[rr] = 0ull;

        #pragma unroll
        for (int ii = 0; ii < 7; ii++) {
            const int ci = lane + (ii << 5);            // uint4 column index (k = 8*ci)
            const double2 hA = h2d[ci * 2];
            const double2 hB = h2d[ci * 2 + 1];
            const unsigned long long hp0 = __double_as_longlong(hA.x);
            const unsigned long long hp1 = __double_as_longlong(hA.y);
            const unsigned long long hp2 = __double_as_longlong(hB.x);
            const unsigned long long hp3 = __double_as_longlong(hB.y);
            const char* wp = wbase + ci * 16;
            #pragma unroll
            for (int rr = 0; rr < 7; rr++) {
                const uint4 wv = *(const uint4*)(wp + rr * ROW_B);
                fma2_bf(wv.x, hp0, a[rr]);
                fma2_bf(wv.y, hp1, a[rr]);
                fma2_bf(wv.z, hp2, a[rr]);
                fma2_bf(wv.w, hp3, a[rr]);
            }
        }
        {   // tail: k = K_SM + lane*8 (prefetched)
            const int ci = (K_SM >> 3) + lane;
            const double2 hA = h2d[ci * 2];
            const double2 hB = h2d[ci * 2 + 1];
            const unsigned long long hp0 = __double_as_longlong(hA.x);
            const unsigned long long hp1 = __double_as_longlong(hA.y);
            const unsigned long long hp2 = __double_as_longlong(hB.x);
            const unsigned long long hp3 = __double_as_longlong(hB.y);
            #pragma unroll
            for (int rr = 0; rr < 7; rr++) {
                fma2_bf(tw[rr].x, hp0, a[rr]);
                fma2_bf(tw[rr].y, hp1, a[rr]);
                fma2_bf(tw[rr].z, hp2, a[rr]);
                fma2_bf(tw[rr].w, hp3, a[rr]);
            }
        }

        // warp-reduce each row; row owner lane writes z to SMEM
        float zv[7];
        #pragma unroll
        for (int rr = 0; rr < 7; rr++) zv[rr] = acc2_sum(a[rr]);
        #pragma unroll
        for (int rr = 0; rr < 7; rr++) {
            #pragma unroll
            for (int off = 16; off > 0; off >>= 1)
                zv[rr] += __shfl_xor_sync(0xffffffffu, zv[rr], off);
        }
        #pragma unroll
        for (int rr = 0; rr < 7; rr++)
            if (lane == rr) zbuf[r0 + rr] = zv[rr];
        __syncthreads();                       // all dots done; zbuf complete; h_sm reads finished

        // warp 0: gates + cell update + publish (st.cg)
        if (w == 0 && lane < nu) {
            const float4 zz = *(const float4*)&zbuf[4 * lane];
            const float ig = sigmoid_f(zz.x + gz.x);
            const float fg = sigmoid_f(zz.y + gz.y);
            const float gg = tanh_f   (zz.z + gz.z);
            const float og = sigmoid_f(zz.w + gz.w);
            const float cn = fg * cst + ig * gg;
            cst = cn;
            const float hn = og * tanh_f(cn);
            const int j = u0 + lane;
            __stcg(&d_hbuf[t & 1][j], hn);
            d_hs[(size_t)t * HID + j] = hn;
            if (t == SEQ - 1) d_cfinal[j] = cn;
        }

        if (t == SEQ - 1) break;               // no more cross-CTA exchange needed

        // grid barrier: fire-and-forget release arrival, acquire poll on monotonic counter
        __syncthreads();                       // h stores done CTA-wide
        if (tid == 0) {
            red_add_release(&d_stepcnt);
            const unsigned long long target = cbase + (unsigned long long)(t + 1) * (unsigned)gridDim.x;
            while (ld_acq64(&d_stepcnt) < target) { }
        }
        __syncthreads();                       // barrier observed CTA-wide

        // gather the full new h into SMEM (L2, bypass L1): 2 float4 per thread
        {
            float4* __restrict__ dst4 = (float4*)h_sm;
            const float4* __restrict__ s4 = (const float4*)d_hbuf[t & 1];
            #pragma unroll
            for (int kk = 0; kk < 2; kk++)
                dst4[tid + kk * NTHREADS] = __ldcg(&s4[tid + kk * NTHREADS]);
        }
        __syncthreads();                       // h(t) fully in SMEM for next dots
    }
}

// ============================================================================
// Kernel 4: out = hs @ V_w + V_b   (8192x2048 @ 2048x256)
// ============================================================================
__global__ void __launch_bounds__(256) out_gemm_kernel(const float* __restrict__ Vw,
                                                       const float* __restrict__ Vb,
                                                       float* __restrict__ out)
{
    __shared__ float As[16][64];
    __shared__ float Bs[16][64];
    const int tid = threadIdx.x;
    const int tx = tid & 15, ty = tid >> 4;
    const int m0 = blockIdx.x * 64, n0 = blockIdx.y * 64;

    float acc[4][4];
    #pragma unroll
    for (int i = 0; i < 4; i++)
        #pragma unroll
        for (int j = 0; j < 4; j++) acc[i][j] = 0.f;

    const int ar = tid >> 2, ac = (tid & 3) * 4;
    const int br = tid >> 4, bc = (tid & 15) * 4;

    for (int k0 = 0; k0 < HID; k0 += 16) {
        const float4 av = *(const float4*)&d_hs[(size_t)(m0 + ar) * HID + k0 + ac];
        As[ac + 0][ar] = av.x; As[ac + 1][ar] = av.y;
        As[ac + 2][ar] = av.z; As[ac + 3][ar] = av.w;
        *(float4*)&Bs[br][bc] = *(const float4*)&Vw[(size_t)(k0 + br) * OUTN + n0 + bc];
        __syncthreads();
        #pragma unroll
        for (int kk = 0; kk < 16; kk++) {
            float a4[4], b4[4];
            *(float4*)a4 = *(const float4*)&As[kk][ty * 4];
            *(float4*)b4 = *(const float4*)&Bs[kk][tx * 4];
            #pragma unroll
            for (int i = 0; i < 4; i++)
                #pragma unroll
                for (int j = 0; j < 4; j++)
                    acc[i][j] = fmaf(a4[i], b4[j], acc[i][j]);
        }
        __syncthreads();
    }
    #pragma unroll
    for (int i = 0; i < 4; i++) {
        #pragma unroll
        for (int j = 0; j < 4; j++) {
            const int oo = n0 + tx * 4 + j;
            out[(size_t)(m0 + ty * 4 + i) * OUTN + oo] = acc[i][j] + Vb[oo];
        }
    }
}

// ============================================================================
// Kernel 5: optional tail (h_T, c_T) if harness expects them appended
// ============================================================================
__global__ void tail_copy_kernel(float* __restrict__ out)
{
    const int i = blockIdx.x * blockDim.x + threadIdx.x;
    if (i < HID) {
        out[(size_t)SEQ * OUTN + i]       = d_hs[(size_t)(SEQ - 1) * HID + i];
        out[(size_t)SEQ * OUTN + HID + i] = d_cfinal[i];
    }
}

// ============================================================================
// host launcher
// inputs: 0:x 1:emb 2:W_i 3:b_i 4:U_i 5:c_i 6:W_f 7:b_f 8:U_f 9:c_f
//         10:W_g 11:b_g 12:U_g 13:c_g 14:W_o 15:b_o 16:U_o 17:c_o 18:V_w 19:V_b
// ============================================================================
extern "C" void kernel_launch(void* const* d_in, const int* in_sizes, int n_in,
                              void* d_out, int out_size)
{
    const int*   x   = (const int*)d_in[0];
    const float* emb = (const float*)d_in[1];

    GateArgs ga;
    UArgs ua;
    ga.W[0] = (const float*)d_in[2];  ga.b[0] = (const float*)d_in[3];
    ua.U[0] = (const float*)d_in[4];  ga.cb[0] = (const float*)d_in[5];
    ga.W[1] = (const float*)d_in[6];  ga.b[1] = (const float*)d_in[7];
    ua.U[1] = (const float*)d_in[8];  ga.cb[1] = (const float*)d_in[9];
    ga.W[2] = (const float*)d_in[10]; ga.b[2] = (const float*)d_in[11];
    ua.U[2] = (const float*)d_in[12]; ga.cb[2] = (const float*)d_in[13];
    ga.W[3] = (const float*)d_in[14]; ga.b[3] = (const float*)d_in[15];
    ua.U[3] = (const float*)d_in[16]; ga.cb[3] = (const float*)d_in[17];
    const float* Vw = (const float*)d_in[18];
    const float* Vb = (const float*)d_in[19];
    float* out = (float*)d_out;

    cudaFuncSetAttribute(lstm_recur_kernel,
                         cudaFuncAttributeMaxDynamicSharedMemorySize, SMEM_RECUR);

    prep_tables_kernel<<<dim3(VOCAB / 8, 4), 256>>>(emb, ga);
    prep_weights_kernel<<<dim3(HID / 32, HID / 32, 4), dim3(32, 32)>>>(ua);
    nop_kernel<<<1, 32>>>();
    lstm_recur_kernel<<<NCTA, NTHREADS, SMEM_RECUR>>>(x);   // ncu -s 5 target
    out_gemm_kernel<<<dim3(SEQ / 64, OUTN / 64), 256>>>(Vw, Vb, out);
    if (out_size >= SEQ * OUTN + 2 * HID)
        tail_copy_kernel<<<(HID + 255) / 256, 256>>>(out);
}